// round 1
// baseline (speedup 1.0000x reference)
#include <cuda_runtime.h>
#include <cuda_bf16.h>
#include <cstdint>

// Problem constants (fixed shapes)
#define TN   32768      // total nodes = B*N
#define D    128        // embedding dim
#define BG   64         // graphs
#define NG   512        // nodes per graph
#define ET   524288     // total edges = B*E
#define NH   4          // heads
#define DHD  32         // head dim

// ---------------- scratch (device globals; no allocation allowed) ----------------
__device__ float g_h  [TN * D];
__device__ float g_h2 [TN * D];
__device__ float g_q  [TN * D];
__device__ float g_k  [TN * D];
__device__ float g_v  [TN * D];
__device__ float g_ao [TN * D];
__device__ float g_deg[TN];          // out-degree + 1 (float)
__device__ int   g_cnt[TN];          // in-degree counts (CSR by dst)
__device__ int   g_start[TN + 1];    // CSR row starts
__device__ int   g_cursor[TN];       // scatter cursors
__device__ int   g_esorted[ET];      // edge ids sorted by dst

// ---------------- init ----------------
__global__ void init_kernel() {
    int i = blockIdx.x * blockDim.x + threadIdx.x;
    if (i < TN) { g_deg[i] = 1.0f; g_cnt[i] = 0; }
}

// ---------------- edge counting: out-degree (for norm) + in-degree (for CSR) ----------------
__global__ void count_kernel(const int* __restrict__ ei) {
    int e = blockIdx.x * blockDim.x + threadIdx.x;
    if (e < ET) {
        int r = ei[e];
        int c = ei[ET + e];
        atomicAdd(&g_deg[r], 1.0f);
        atomicAdd(&g_cnt[c], 1);
    }
}

// ---------------- single-block prefix scan over 32768 counts ----------------
__global__ void scan_kernel() {
    __shared__ int ps[1024];
    int t = threadIdx.x;
    int base = t * 32;
    int c[32];
    int s = 0;
#pragma unroll
    for (int i = 0; i < 32; i++) { c[i] = g_cnt[base + i]; s += c[i]; }
    ps[t] = s;
    __syncthreads();
    // Kogge-Stone inclusive scan over 1024 partials
    for (int off = 1; off < 1024; off <<= 1) {
        int v = (t >= off) ? ps[t - off] : 0;
        __syncthreads();
        ps[t] += v;
        __syncthreads();
    }
    int run = ps[t] - s;   // exclusive base for this thread's chunk
#pragma unroll
    for (int i = 0; i < 32; i++) {
        g_start[base + i]  = run;
        g_cursor[base + i] = run;
        run += c[i];
    }
    if (t == 1023) g_start[TN] = run;
}

// ---------------- scatter edge ids into CSR slots ----------------
__global__ void scatter_kernel(const int* __restrict__ ei) {
    int e = blockIdx.x * blockDim.x + threadIdx.x;
    if (e < ET) {
        int c = ei[ET + e];
        int pos = atomicAdd(&g_cursor[c], 1);
        g_esorted[pos] = e;
    }
}

// ---------------- gather + finalize: h2 = agg + relu(h + root)/deg ----------------
// one warp per destination node; lane owns 4 features (float4)
__global__ void gather_kernel(const int* __restrict__ ei,
                              const float* __restrict__ ee,
                              const float* __restrict__ root) {
    int gw = (blockIdx.x * blockDim.x + threadIdx.x) >> 5;
    int lane = threadIdx.x & 31;
    if (gw >= TN) return;
    int n = gw;
    float degn = g_deg[n];
    float dc = rsqrtf(degn);
    const float4* h4 = (const float4*)g_h;
    const float4* e4 = (const float4*)ee;
    float4 acc = make_float4(0.f, 0.f, 0.f, 0.f);
    int s = g_start[n];
    int t = g_start[n + 1];
    for (int p = s; p < t; ++p) {
        int eid = g_esorted[p];
        int r = ei[eid];
        float norm = dc * rsqrtf(g_deg[r]);
        float4 hv = h4[r * 32 + lane];
        float4 ev = e4[(long long)eid * 32 + lane];
        acc.x += norm * fmaxf(hv.x + ev.x, 0.f);
        acc.y += norm * fmaxf(hv.y + ev.y, 0.f);
        acc.z += norm * fmaxf(hv.z + ev.z, 0.f);
        acc.w += norm * fmaxf(hv.w + ev.w, 0.f);
    }
    float4 hs = h4[n * 32 + lane];
    float4 rt = ((const float4*)root)[lane];
    float inv = 1.0f / degn;
    acc.x += fmaxf(hs.x + rt.x, 0.f) * inv;
    acc.y += fmaxf(hs.y + rt.y, 0.f) * inv;
    acc.z += fmaxf(hs.z + rt.z, 0.f) * inv;
    acc.w += fmaxf(hs.w + rt.w, 0.f) * inv;
    ((float4*)g_h2)[n * 32 + lane] = acc;
}

// ---------------- generic (M x 128) @ (128 x 128-col-tile) GEMM ----------------
// 64 rows per block, 256 threads, full K=128 in one pass; dyn smem = 96KB
__global__ void gemm128_kernel(const float* __restrict__ A,
                               const float* __restrict__ W, int wld, int wcol0,
                               const float* __restrict__ bias,
                               float* __restrict__ out) {
    extern __shared__ float sm[];
    float* As = sm;                 // 64*128
    float* Ws = sm + 64 * 128;      // 128*128
    int tid = threadIdx.x;
    long long m0 = (long long)blockIdx.x * 64;

    const float4* A4 = (const float4*)(A + m0 * 128);
    float4* As4 = (float4*)As;
#pragma unroll
    for (int i = 0; i < 8; i++) As4[tid + i * 256] = A4[tid + i * 256];

    float4* Ws4 = (float4*)Ws;
#pragma unroll
    for (int i = 0; i < 16; i++) {
        int idx = tid + i * 256;        // 0..4095 float4
        int k  = idx >> 5;
        int c4 = idx & 31;
        Ws4[idx] = *(const float4*)(W + k * wld + wcol0 + c4 * 4);
    }
    __syncthreads();

    int r0 = (tid >> 5) * 8;
    int cl = (tid & 31);
    float4 acc[8];
#pragma unroll
    for (int i = 0; i < 8; i++) acc[i] = make_float4(0.f, 0.f, 0.f, 0.f);

#pragma unroll 4
    for (int k = 0; k < 128; k++) {
        float4 w = Ws4[k * 32 + cl];
#pragma unroll
        for (int i = 0; i < 8; i++) {
            float a = As[(r0 + i) * 128 + k];
            acc[i].x += a * w.x;
            acc[i].y += a * w.y;
            acc[i].z += a * w.z;
            acc[i].w += a * w.w;
        }
    }

    float4 bv = make_float4(0.f, 0.f, 0.f, 0.f);
    if (bias) bv = *(const float4*)(bias + wcol0 + cl * 4);
    float4* O4 = (float4*)(out + m0 * 128);
#pragma unroll
    for (int i = 0; i < 8; i++) {
        float4 v = acc[i];
        v.x += bv.x; v.y += bv.y; v.z += bv.z; v.w += bv.w;
        O4[(r0 + i) * 32 + cl] = v;
    }
}

// ---------------- attention: per (b,h,qtile) block; flash-style online softmax ----------------
// 256 threads, 256 queries/block (1 per thread), full K/V (512x32 fp32 each) in smem = 128KB
__global__ void attn_kernel() {
    extern __shared__ float sm[];
    float4* Ks4 = (float4*)sm;          // 512*8 float4
    float4* Vs4 = Ks4 + 512 * 8;
    int tid = threadIdx.x;
    int bi = blockIdx.x;
    int b  = bi >> 3;
    int h  = (bi >> 1) & 3;
    int qt = bi & 1;
    int nbase = b * NG;

    const float4* K4 = (const float4*)g_k;
    const float4* V4 = (const float4*)g_v;
    for (int idx = tid; idx < NG * 8; idx += 256) {
        int j  = idx >> 3;
        int d4 = idx & 7;
        Ks4[idx] = K4[(nbase + j) * 32 + h * 8 + d4];
        Vs4[idx] = V4[(nbase + j) * 32 + h * 8 + d4];
    }
    __syncthreads();

    int i = qt * 256 + tid;
    float q[32];
    {
        const float4* Q4 = (const float4*)g_q;
        const float scale = 0.17677669529663687f;   // 1/sqrt(32)
#pragma unroll
        for (int d4 = 0; d4 < 8; d4++) {
            float4 t4 = Q4[(nbase + i) * 32 + h * 8 + d4];
            q[4 * d4 + 0] = t4.x * scale;
            q[4 * d4 + 1] = t4.y * scale;
            q[4 * d4 + 2] = t4.z * scale;
            q[4 * d4 + 3] = t4.w * scale;
        }
    }

    float o[32];
#pragma unroll
    for (int d = 0; d < 32; d++) o[d] = 0.f;
    float m = -1e30f, l = 0.f;

    for (int jt = 0; jt < NG; jt += 16) {
        float s[16];
#pragma unroll
        for (int jj = 0; jj < 16; jj++) {
            float acc = 0.f;
#pragma unroll
            for (int d4 = 0; d4 < 8; d4++) {
                float4 kk = Ks4[(jt + jj) * 8 + d4];
                acc += q[4 * d4 + 0] * kk.x + q[4 * d4 + 1] * kk.y
                     + q[4 * d4 + 2] * kk.z + q[4 * d4 + 3] * kk.w;
            }
            s[jj] = acc;
        }
        float tm = s[0];
#pragma unroll
        for (int jj = 1; jj < 16; jj++) tm = fmaxf(tm, s[jj]);
        float nm = fmaxf(m, tm);
        float alpha = __expf(m - nm);
        l *= alpha;
#pragma unroll
        for (int d = 0; d < 32; d++) o[d] *= alpha;
#pragma unroll
        for (int jj = 0; jj < 16; jj++) {
            float p = __expf(s[jj] - nm);
            l += p;
#pragma unroll
            for (int d4 = 0; d4 < 8; d4++) {
                float4 vv = Vs4[(jt + jj) * 8 + d4];
                o[4 * d4 + 0] += p * vv.x;
                o[4 * d4 + 1] += p * vv.y;
                o[4 * d4 + 2] += p * vv.z;
                o[4 * d4 + 3] += p * vv.w;
            }
        }
        m = nm;
    }

    float inv = 1.0f / l;
    float4* O4 = (float4*)g_ao;
#pragma unroll
    for (int d4 = 0; d4 < 8; d4++) {
        float4 v;
        v.x = o[4 * d4 + 0] * inv;
        v.y = o[4 * d4 + 1] * inv;
        v.z = o[4 * d4 + 2] * inv;
        v.w = o[4 * d4 + 3] * inv;
        O4[(nbase + i) * 32 + h * 8 + d4] = v;
    }
}

// ---------------- launch ----------------
extern "C" void kernel_launch(void* const* d_in, const int* in_sizes, int n_in,
                              void* d_out, int out_size) {
    const float* x    = (const float*)d_in[0];
    const int*   ei   = (const int*)d_in[1];
    const float* ee   = (const float*)d_in[2];
    // d_in[3] = batch (unused: uniform graph sizes)
    const float* Wg   = (const float*)d_in[4];
    const float* bg   = (const float*)d_in[5];
    const float* root = (const float*)d_in[6];
    const float* Wq   = (const float*)d_in[7];
    const float* Wkv  = (const float*)d_in[8];
    const float* Wo   = (const float*)d_in[9];
    const float* bo   = (const float*)d_in[10];
    float* outp = (float*)d_out;

    // scratch addresses
    float *p_h, *p_h2, *p_q, *p_k, *p_v, *p_ao;
    cudaGetSymbolAddress((void**)&p_h,  g_h);
    cudaGetSymbolAddress((void**)&p_h2, g_h2);
    cudaGetSymbolAddress((void**)&p_q,  g_q);
    cudaGetSymbolAddress((void**)&p_k,  g_k);
    cudaGetSymbolAddress((void**)&p_v,  g_v);
    cudaGetSymbolAddress((void**)&p_ao, g_ao);

    cudaFuncSetAttribute(gemm128_kernel, cudaFuncAttributeMaxDynamicSharedMemorySize, 96 * 1024);
    cudaFuncSetAttribute(attn_kernel,    cudaFuncAttributeMaxDynamicSharedMemorySize, 128 * 1024);

    // 1) init counters
    init_kernel<<<TN / 256, 256>>>();
    // 2) h = x @ W_gcn + b_gcn
    gemm128_kernel<<<TN / 64, 256, 96 * 1024>>>(x, Wg, 128, 0, bg, p_h);
    // 3) degree counts
    count_kernel<<<ET / 256, 256>>>(ei);
    // 4) prefix scan -> CSR starts
    scan_kernel<<<1, 1024>>>();
    // 5) scatter edge ids by destination
    scatter_kernel<<<ET / 256, 256>>>(ei);
    // 6) gather messages + self term -> h2
    gather_kernel<<<TN / 8, 256>>>(ei, ee, root);
    // 7) q, k, v projections
    gemm128_kernel<<<TN / 64, 256, 96 * 1024>>>(p_h2, Wq, 128, 0, nullptr, p_q);
    gemm128_kernel<<<TN / 64, 256, 96 * 1024>>>(p_h2, Wkv, 256, 0, nullptr, p_k);
    gemm128_kernel<<<TN / 64, 256, 96 * 1024>>>(p_h2, Wkv, 256, 128, nullptr, p_v);
    // 8) masked (all-true) self-attention per graph
    attn_kernel<<<BG * NH * 2, 256, 128 * 1024>>>();
    // 9) out = ao @ Wout + b_out
    gemm128_kernel<<<TN / 64, 256, 96 * 1024>>>(p_ao, Wo, 128, 0, bo, outp);
}

// round 2
// speedup vs baseline: 1.1504x; 1.1504x over previous
#include <cuda_runtime.h>
#include <cuda_bf16.h>
#include <cstdint>

#define TN   32768
#define D    128
#define BG   64
#define NG   512
#define ET   524288
#define NH   4

typedef unsigned long long u64;

// ---------------- scratch ----------------
__device__ float g_h  [TN * D];
__device__ float g_h2 [TN * D];
__device__ float g_q  [TN * D];
__device__ float g_kv [TN * 256];
__device__ float g_ao [TN * D];
__device__ float g_wt [256 * 128];   // transposed weights (reused serially)
__device__ float g_deg[TN];
__device__ float g_dinv[TN];
__device__ int   g_cnt[TN];
__device__ int   g_start[TN + 1];
__device__ int   g_cursor[TN];
__device__ int   g_esorted[ET];
__device__ int   g_esrc[ET];

// ---------------- f32x2 helpers ----------------
#define FMA2(d,a,b) asm("fma.rn.f32x2 %0, %1, %2, %0;" : "+l"(d) : "l"(a), "l"(b))
#define MUL2(d,a)   asm("mul.rn.f32x2 %0, %0, %1;"     : "+l"(d) : "l"(a))

__device__ __forceinline__ u64 pk2(float lo, float hi) {
    u64 r;
    asm("mov.b64 %0, {%1, %2};" : "=l"(r)
        : "r"(__float_as_uint(lo)), "r"(__float_as_uint(hi)));
    return r;
}
__device__ __forceinline__ float hadd2(u64 v) {
    unsigned int lo, hi;
    asm("mov.b64 {%0, %1}, %2;" : "=r"(lo), "=r"(hi) : "l"(v));
    return __uint_as_float(lo) + __uint_as_float(hi);
}

// ---------------- init ----------------
__global__ void init_kernel() {
    int i = blockIdx.x * blockDim.x + threadIdx.x;
    if (i < TN) { g_deg[i] = 1.0f; g_cnt[i] = 0; }
}

__global__ void count_kernel(const int* __restrict__ ei) {
    int e = blockIdx.x * blockDim.x + threadIdx.x;
    if (e < ET) {
        atomicAdd(&g_deg[ei[e]], 1.0f);
        atomicAdd(&g_cnt[ei[ET + e]], 1);
    }
}

__global__ void dinv_kernel() {
    int i = blockIdx.x * blockDim.x + threadIdx.x;
    if (i < TN) g_dinv[i] = rsqrtf(g_deg[i]);
}

// ---------------- fast single-block scan (shuffle based) ----------------
__global__ void scan_kernel() {
    __shared__ int wsum[32];
    int t = threadIdx.x;
    int lane = t & 31, wid = t >> 5;
    const int4* cnt4 = (const int4*)g_cnt;
    int4 c4[8];
    int s = 0;
#pragma unroll
    for (int i = 0; i < 8; i++) {
        c4[i] = cnt4[t * 8 + i];
        s += c4[i].x + c4[i].y + c4[i].z + c4[i].w;
    }
    int v = s;
#pragma unroll
    for (int off = 1; off < 32; off <<= 1) {
        int u = __shfl_up_sync(0xffffffffu, v, off);
        if (lane >= off) v += u;
    }
    if (lane == 31) wsum[wid] = v;
    __syncthreads();
    if (wid == 0) {
        int w = wsum[lane];
#pragma unroll
        for (int off = 1; off < 32; off <<= 1) {
            int u = __shfl_up_sync(0xffffffffu, w, off);
            if (lane >= off) w += u;
        }
        wsum[lane] = w;
    }
    __syncthreads();
    int base = (v - s) + (wid ? wsum[wid - 1] : 0);
#pragma unroll
    for (int i = 0; i < 8; i++) {
        int idx = t * 32 + i * 4;
        int4 c = c4[i];
        g_start[idx]     = base; g_cursor[idx]     = base; base += c.x;
        g_start[idx + 1] = base; g_cursor[idx + 1] = base; base += c.y;
        g_start[idx + 2] = base; g_cursor[idx + 2] = base; base += c.z;
        g_start[idx + 3] = base; g_cursor[idx + 3] = base; base += c.w;
    }
    if (t == 1023) g_start[TN] = base;
}

__global__ void scatter_kernel(const int* __restrict__ ei) {
    int e = blockIdx.x * blockDim.x + threadIdx.x;
    if (e < ET) {
        int r = ei[e];
        int c = ei[ET + e];
        int pos = atomicAdd(&g_cursor[c], 1);
        g_esorted[pos] = e;
        g_esrc[pos] = r;
    }
}

// ---------------- gather + finalize ----------------
__global__ void gather_kernel(const float* __restrict__ ee,
                              const float* __restrict__ root) {
    int gw = (blockIdx.x * blockDim.x + threadIdx.x) >> 5;
    int lane = threadIdx.x & 31;
    if (gw >= TN) return;
    int n = gw;
    float degn = g_deg[n];
    float dc = g_dinv[n];
    const float4* h4 = (const float4*)g_h;
    const float4* e4 = (const float4*)ee;
    float4 acc = make_float4(0.f, 0.f, 0.f, 0.f);
    int s = g_start[n];
    int t = g_start[n + 1];
    for (int p = s; p < t; ++p) {
        int eid = g_esorted[p];
        int r   = g_esrc[p];
        float norm = dc * g_dinv[r];
        float4 hv = h4[r * 32 + lane];
        float4 ev = e4[(long long)eid * 32 + lane];
        acc.x += norm * fmaxf(hv.x + ev.x, 0.f);
        acc.y += norm * fmaxf(hv.y + ev.y, 0.f);
        acc.z += norm * fmaxf(hv.z + ev.z, 0.f);
        acc.w += norm * fmaxf(hv.w + ev.w, 0.f);
    }
    float4 hs = h4[n * 32 + lane];
    float4 rt = ((const float4*)root)[lane];
    float inv = 1.0f / degn;
    acc.x += fmaxf(hs.x + rt.x, 0.f) * inv;
    acc.y += fmaxf(hs.y + rt.y, 0.f) * inv;
    acc.z += fmaxf(hs.z + rt.z, 0.f) * inv;
    acc.w += fmaxf(hs.w + rt.w, 0.f) * inv;
    ((float4*)g_h2)[n * 32 + lane] = acc;
}

// ---------------- weight transpose: WT[c][k] = W[k][c] ----------------
__global__ void wtrans_kernel(const float* __restrict__ W, float* __restrict__ WT, int ncols) {
    __shared__ float t[32][33];
    int c = blockIdx.x * 32 + threadIdx.x;
    int k = blockIdx.y * 32 + threadIdx.y;
#pragma unroll
    for (int i = 0; i < 32; i += 8)
        t[threadIdx.y + i][threadIdx.x] = W[(k + i) * ncols + c];
    __syncthreads();
    int c2 = blockIdx.x * 32 + threadIdx.y;
    int k2 = blockIdx.y * 32 + threadIdx.x;
#pragma unroll
    for (int i = 0; i < 32; i += 8)
        WT[(c2 + i) * 128 + k2] = t[threadIdx.x][threadIdx.y + i];
}

// ---------------- GEMM: (M x 128) @ (128 x ncols), 128x64 tile/block, f32x2 ----------------
// A row-major in smem, WT[c][k] padded stride 130 floats (65 u64).
__global__ void __launch_bounds__(256, 2)
gemm_kernel(const float* __restrict__ A, const float* __restrict__ WT,
            int ncols, const float* __restrict__ bias, float* __restrict__ out) {
    extern __shared__ float sm[];
    float* As  = sm;             // 128*128 floats = 64KB
    float* WsT = sm + 128 * 128; // 64*130 floats  = 33.3KB
    int tid = threadIdx.x;
    long long m0 = (long long)blockIdx.x * 128;
    int cb = blockIdx.y * 64;

    const float4* A4 = (const float4*)(A + m0 * 128);
    float4* As4 = (float4*)As;
#pragma unroll
    for (int i = 0; i < 16; i++) As4[tid + i * 256] = A4[tid + i * 256];

    const float4* WT4 = (const float4*)(g_wt + cb * 128);
    (void)WT;
#pragma unroll
    for (int i = 0; i < 8; i++) {
        int idx = tid + i * 256;       // over 64 c x 32 k4
        int c  = idx >> 5;
        int k4 = idx & 31;
        float4 w = WT4[idx];
        u64* dst = (u64*)(WsT + c * 130 + k4 * 4);
        dst[0] = ((const u64*)&w)[0];
        dst[1] = ((const u64*)&w)[1];
    }
    __syncthreads();

    int cg = tid & 15;          // 16 col groups of 4
    int rg = tid >> 4;          // 16 row groups of 8
    int c0 = cg * 4, r0 = rg * 8;

    u64 acc[8][4];
#pragma unroll
    for (int i = 0; i < 8; i++)
#pragma unroll
        for (int j = 0; j < 4; j++) acc[i][j] = 0ull;

    const u64* Au = (const u64*)As;    // [r][kk], stride 64 u64
    const u64* Wu = (const u64*)WsT;   // [c][kk], stride 65 u64

#pragma unroll 4
    for (int kk = 0; kk < 64; kk++) {
        u64 w2[4];
#pragma unroll
        for (int ci = 0; ci < 4; ci++) w2[ci] = Wu[(c0 + ci) * 65 + kk];
#pragma unroll
        for (int ri = 0; ri < 8; ri++) {
            u64 a2 = Au[(r0 + ri) * 64 + kk];
#pragma unroll
            for (int ci = 0; ci < 4; ci++) FMA2(acc[ri][ci], a2, w2[ci]);
        }
    }

    float4 bv = make_float4(0.f, 0.f, 0.f, 0.f);
    if (bias) bv = ((const float4*)bias)[(cb >> 2) + cg];
    float4* O4 = (float4*)out;
    int row_ld = ncols >> 2;
#pragma unroll
    for (int ri = 0; ri < 8; ri++) {
        float4 o;
        o.x = hadd2(acc[ri][0]) + bv.x;
        o.y = hadd2(acc[ri][1]) + bv.y;
        o.z = hadd2(acc[ri][2]) + bv.z;
        o.w = hadd2(acc[ri][3]) + bv.w;
        O4[(m0 + r0 + ri) * row_ld + (cb >> 2) + cg] = o;
    }
}

// ---------------- attention: one block per (b,h), 256 thr, 2 queries/thread, f32x2 ----------------
__global__ void __launch_bounds__(256) attn_kernel() {
    extern __shared__ float sm[];
    float4* Ks4 = (float4*)sm;          // 512*8 float4 = 64KB
    float4* Vs4 = Ks4 + 512 * 8;        // 64KB
    int tid = threadIdx.x;
    int b = blockIdx.x >> 2;
    int h = blockIdx.x & 3;
    int nbase = b * NG;

    const float4* KV4 = (const float4*)g_kv;   // row stride 64 float4
    for (int idx = tid; idx < NG * 8; idx += 256) {
        int j  = idx >> 3;
        int d4 = idx & 7;
        Ks4[idx] = KV4[(nbase + j) * 64 + h * 8 + d4];
        Vs4[idx] = KV4[(nbase + j) * 64 + 32 + h * 8 + d4];
    }
    __syncthreads();

    const float scale = 0.17677669529663687f;
    u64 q0[16], q1[16];
    const float4* Q4 = (const float4*)g_q;
#pragma unroll
    for (int d4 = 0; d4 < 8; d4++) {
        float4 a = Q4[(nbase + tid) * 32 + h * 8 + d4];
        q0[2 * d4]     = pk2(a.x * scale, a.y * scale);
        q0[2 * d4 + 1] = pk2(a.z * scale, a.w * scale);
        float4 c = Q4[(nbase + tid + 256) * 32 + h * 8 + d4];
        q1[2 * d4]     = pk2(c.x * scale, c.y * scale);
        q1[2 * d4 + 1] = pk2(c.z * scale, c.w * scale);
    }

    u64 o0[16], o1[16];
#pragma unroll
    for (int d = 0; d < 16; d++) { o0[d] = 0ull; o1[d] = 0ull; }
    float m0 = -1e30f, l0 = 0.f, m1 = -1e30f, l1 = 0.f;

    for (int jt = 0; jt < NG; jt += 8) {
        float s0[8], s1[8];
#pragma unroll
        for (int jj = 0; jj < 8; jj++) {
            const ulonglong2* kp = (const ulonglong2*)(Ks4 + (jt + jj) * 8);
            u64 a0 = 0ull, b0 = 0ull, a1 = 0ull, b1 = 0ull;
#pragma unroll
            for (int d = 0; d < 8; d++) {
                ulonglong2 kk = kp[d];
                FMA2(a0, q0[2 * d], kk.x);
                FMA2(b0, q0[2 * d + 1], kk.y);
                FMA2(a1, q1[2 * d], kk.x);
                FMA2(b1, q1[2 * d + 1], kk.y);
            }
            s0[jj] = hadd2(a0) + hadd2(b0);
            s1[jj] = hadd2(a1) + hadd2(b1);
        }
        float tm0 = s0[0], tm1 = s1[0];
#pragma unroll
        for (int jj = 1; jj < 8; jj++) { tm0 = fmaxf(tm0, s0[jj]); tm1 = fmaxf(tm1, s1[jj]); }
        float nm0 = fmaxf(m0, tm0), nm1 = fmaxf(m1, tm1);
        float al0 = __expf(m0 - nm0), al1 = __expf(m1 - nm1);
        m0 = nm0; m1 = nm1;
        l0 *= al0; l1 *= al1;
        u64 al0p = pk2(al0, al0), al1p = pk2(al1, al1);
#pragma unroll
        for (int d = 0; d < 16; d++) { MUL2(o0[d], al0p); MUL2(o1[d], al1p); }
#pragma unroll
        for (int jj = 0; jj < 8; jj++) {
            float p0 = __expf(s0[jj] - m0); l0 += p0;
            float p1 = __expf(s1[jj] - m1); l1 += p1;
            u64 p0p = pk2(p0, p0), p1p = pk2(p1, p1);
            const ulonglong2* vp = (const ulonglong2*)(Vs4 + (jt + jj) * 8);
#pragma unroll
            for (int d = 0; d < 8; d++) {
                ulonglong2 vv = vp[d];
                FMA2(o0[2 * d],     p0p, vv.x);
                FMA2(o0[2 * d + 1], p0p, vv.y);
                FMA2(o1[2 * d],     p1p, vv.x);
                FMA2(o1[2 * d + 1], p1p, vv.y);
            }
        }
    }

    float inv0 = 1.0f / l0, inv1 = 1.0f / l1;
    u64 i0p = pk2(inv0, inv0), i1p = pk2(inv1, inv1);
    ulonglong2* O = (ulonglong2*)g_ao;  // row = 32 ulonglong2
#pragma unroll
    for (int d = 0; d < 8; d++) {
        MUL2(o0[2 * d], i0p); MUL2(o0[2 * d + 1], i0p);
        MUL2(o1[2 * d], i1p); MUL2(o1[2 * d + 1], i1p);
        O[(nbase + tid) * 32 + h * 8 + d]       = make_ulonglong2(o0[2 * d], o0[2 * d + 1]);
        O[(nbase + tid + 256) * 32 + h * 8 + d] = make_ulonglong2(o1[2 * d], o1[2 * d + 1]);
    }
}

// ---------------- launch ----------------
extern "C" void kernel_launch(void* const* d_in, const int* in_sizes, int n_in,
                              void* d_out, int out_size) {
    const float* x    = (const float*)d_in[0];
    const int*   ei   = (const int*)d_in[1];
    const float* ee   = (const float*)d_in[2];
    const float* Wg   = (const float*)d_in[4];
    const float* bg   = (const float*)d_in[5];
    const float* root = (const float*)d_in[6];
    const float* Wq   = (const float*)d_in[7];
    const float* Wkv  = (const float*)d_in[8];
    const float* Wo   = (const float*)d_in[9];
    const float* bo   = (const float*)d_in[10];
    float* outp = (float*)d_out;

    float *p_h, *p_h2, *p_q, *p_kv, *p_ao, *p_wt;
    cudaGetSymbolAddress((void**)&p_h,  g_h);
    cudaGetSymbolAddress((void**)&p_h2, g_h2);
    cudaGetSymbolAddress((void**)&p_q,  g_q);
    cudaGetSymbolAddress((void**)&p_kv, g_kv);
    cudaGetSymbolAddress((void**)&p_ao, g_ao);
    cudaGetSymbolAddress((void**)&p_wt, g_wt);

    const int GEMM_SMEM = (128 * 128 + 64 * 130) * 4;   // 98816
    cudaFuncSetAttribute(gemm_kernel, cudaFuncAttributeMaxDynamicSharedMemorySize, GEMM_SMEM);
    cudaFuncSetAttribute(attn_kernel, cudaFuncAttributeMaxDynamicSharedMemorySize, 128 * 1024);

    dim3 tb(32, 8);

    // CSR build chain (independent of GEMMs, but stream-ordered)
    init_kernel<<<TN / 256, 256>>>();
    count_kernel<<<ET / 256, 256>>>(ei);
    dinv_kernel<<<TN / 256, 256>>>();
    scan_kernel<<<1, 1024>>>();
    scatter_kernel<<<ET / 256, 256>>>(ei);

    // h = x @ W_gcn + b_gcn
    wtrans_kernel<<<dim3(4, 4), tb>>>(Wg, p_wt, 128);
    gemm_kernel<<<dim3(TN / 128, 2), 256, GEMM_SMEM>>>(x, p_wt, 128, bg, p_h);

    // gather -> h2
    gather_kernel<<<TN / 8, 256>>>(ee, root);

    // q projection
    wtrans_kernel<<<dim3(4, 4), tb>>>(Wq, p_wt, 128);
    gemm_kernel<<<dim3(TN / 128, 2), 256, GEMM_SMEM>>>(p_h2, p_wt, 128, nullptr, p_q);

    // fused kv projection (256 cols)
    wtrans_kernel<<<dim3(8, 4), tb>>>(Wkv, p_wt, 256);
    gemm_kernel<<<dim3(TN / 128, 4), 256, GEMM_SMEM>>>(p_h2, p_wt, 256, nullptr, p_kv);

    // attention
    attn_kernel<<<BG * NH, 256, 128 * 1024>>>();

    // out = ao @ Wout + b_out
    wtrans_kernel<<<dim3(4, 4), tb>>>(Wo, p_wt, 128);
    gemm_kernel<<<dim3(TN / 128, 2), 256, GEMM_SMEM>>>(p_ao, p_wt, 128, bo, outp);
}